// round 15
// baseline (speedup 1.0000x reference)
#include <cuda_runtime.h>
#include <cuda_bf16.h>
#include <math.h>

// Problem constants
#define NB        128
#define NT        256
#define T_STEPS   512
#define BATCH     32
#define IN_SZ     512
#define OUT_SZ    512
#define LHID      512
#define KC        128           // k per chunk (never straddles a 512 region boundary)
#define NCH       12            // 1536 / 128
#define HN_BASE   (BATCH * T_STEPS * OUT_SZ)
#define TOTAL_SYNCS 1537u       // 1 + 3*T_STEPS

// Persistent state (device globals; no allocation allowed)
__device__ float g_hbuf[2][2][2][BATCH][LHID];
__device__ float g_c[2][2][BATCH][LHID];
__device__ float g_prev[BATCH][OUT_SZ];
__device__ volatile unsigned g_flag[NB * 32];
__device__ unsigned g_base = 0;
// Block-contiguous bf16 weight images: [l2d][ugroup][32 rows][1536 k], hi and lo
__device__ __align__(16) __nv_bfloat16 g_whi[4 * 64 * 32 * 1536];   // 25.2 MB
__device__ __align__(16) __nv_bfloat16 g_wlo[4 * 64 * 32 * 1536];   // 25.2 MB

__device__ __forceinline__ void grid_sync_(unsigned gen) {
    __threadfence();
    __syncthreads();
    if (threadIdx.x == 0) g_flag[blockIdx.x * 32] = gen;
    if (threadIdx.x < NB) { while (g_flag[threadIdx.x * 32] < gen) { } }
    __threadfence();
    __syncthreads();
}

__device__ __forceinline__ float sigm(float x) { return 1.0f / (1.0f + expf(-x)); }

__device__ __forceinline__ void cp_async16(void* smem_dst, const void* gsrc) {
    unsigned saddr = (unsigned)__cvta_generic_to_shared(smem_dst);
    asm volatile("cp.async.cg.shared.global [%0], [%1], 16;\n" :: "r"(saddr), "l"(gsrc));
}
__device__ __forceinline__ void cp_commit() { asm volatile("cp.async.commit_group;\n"); }
template <int N> __device__ __forceinline__ void cp_wait() {
    asm volatile("cp.async.wait_group %0;\n" :: "n"(N));
}

__device__ __forceinline__ unsigned short bf2u(__nv_bfloat16 h) {
    return *reinterpret_cast<unsigned short*>(&h);
}
// 8 fp32 -> packed bf16 hi (rounded) and lo (residual), 4+4 u32 words
__device__ __forceinline__ void cvt_hilo8(const float* v, uint4& hp, uint4& lp) {
    unsigned hw[4], lw[4];
    #pragma unroll
    for (int i = 0; i < 4; ++i) {
        __nv_bfloat16 h0 = __float2bfloat16(v[2*i]), h1 = __float2bfloat16(v[2*i+1]);
        float f0 = __bfloat162float(h0), f1 = __bfloat162float(h1);
        __nv_bfloat16 l0 = __float2bfloat16(v[2*i] - f0), l1 = __float2bfloat16(v[2*i+1] - f1);
        hw[i] = (unsigned)bf2u(h0) | ((unsigned)bf2u(h1) << 16);
        lw[i] = (unsigned)bf2u(l0) | ((unsigned)bf2u(l1) << 16);
    }
    hp = make_uint4(hw[0], hw[1], hw[2], hw[3]);
    lp = make_uint4(lw[0], lw[1], lw[2], lw[3]);
}

// HMMA m16n8k16 bf16->f32 (sm_80 PTX; valid on generic sm_103 target)
#define MMA_BF16(d, a, b) \
    asm volatile("mma.sync.aligned.m16n8k16.row.col.f32.bf16.bf16.f32 " \
                 "{%0,%1,%2,%3}, {%4,%5,%6,%7}, {%8,%9}, {%0,%1,%2,%3};" \
                 : "+f"(d[0]), "+f"(d[1]), "+f"(d[2]), "+f"(d[3]) \
                 : "r"(a[0]), "r"(a[1]), "r"(a[2]), "r"(a[3]), "r"(b[0]), "r"(b[1]))
#define LDSM_X4(r, addr) \
    asm volatile("ldmatrix.sync.aligned.m8n8.x4.shared.b16 {%0,%1,%2,%3}, [%4];" \
                 : "=r"(r[0]), "=r"(r[1]), "=r"(r[2]), "=r"(r[3]) : "r"(addr))
#define LDSM_X2(r, addr) \
    asm volatile("ldmatrix.sync.aligned.m8n8.x2.shared.b16 {%0,%1}, [%2];" \
                 : "=r"(r[0]), "=r"(r[1]) : "r"(addr))

// smem float layout:
//   wfc   [0,4096) resident | fcred [4096,4352) | tot [4352,5408) | bias [5408,5472)
//   buffers (bytes from BUF_BYTE): 2 x { Ahi@0, Alo@8704, Bhi@17408, Blo@26112 } (34816 B each)
//   FC overlay: hs [5472, 38368) floats (over the buffer region)
#define WFC_F    0
#define FCRED_F  4096
#define TOT_F    4352
#define BIAS_F   5408
#define HS_F     5472
#define BUF_BYTE 21888          // 5472*4
#define IMG_A_LO 8704
#define IMG_B_HI 17408
#define IMG_B_LO 26112
#define BUFSZB   34816
#define PADR     272            // bf16 row stride in bytes: (128+8)*2 ; 272 % 128 = 16
#define SMEM_BYTES 153472       // 38368 floats

__global__ void __launch_bounds__(NT, 1)
ae_kernel(const float* __restrict__ x_in,
          const float* __restrict__ W_ih, const float* __restrict__ W_hh,
          const float* __restrict__ b_ih, const float* __restrict__ b_hh,
          const float* __restrict__ W_fc, const float* __restrict__ b_fc,
          float* __restrict__ out)
{
    extern __shared__ float sm[];
    char* smc = (char*)sm;
    const int tid = threadIdx.x;
    const int bid = blockIdx.x;
    const int wid = tid >> 5;
    const int lane = tid & 31;
    const unsigned sbase = (unsigned)__cvta_generic_to_shared(sm);
    const unsigned base = g_base;

    // block mapping: 128 blocks = 2 dirs x 64 unit-groups (8 units -> 32 gate rows)
    const int d  = bid >> 6;
    const int ug = bid & 63;
    const int u0 = ug << 3;

    // ---- init state + one-time (idempotent) weight hi/lo image conversion ----
    {
        float* h0 = &g_hbuf[0][0][0][0][0];
        for (int e = bid * NT + tid; e < 2 * 2 * BATCH * LHID; e += NB * NT) h0[e] = 0.0f;
        float* c0 = &g_c[0][0][0][0];
        for (int e = bid * NT + tid; e < 2 * 2 * BATCH * LHID; e += NB * NT) c0[e] = 0.0f;
        float* p0 = &g_prev[0][0];
        for (int e = bid * NT + tid; e < BATCH * OUT_SZ; e += NB * NT) p0[e] = 0.0f;

        // images: row R = ((l2d*64 + ug)*32 + r), r = gate*8 + j -> weight row gate*512+u0+j
        for (int g = bid * NT + tid; g < 4 * 64 * 32 * 192; g += NB * NT) {
            int seg = g % 192, R = g / 192;
            int l2d = R >> 11, ugr = (R >> 5) & 63, r = R & 31;
            int grow = ((r >> 3) << 9) + (ugr << 3) + (r & 7);
            int k0 = seg * 8;
            const float* src = (k0 < 1024)
                ? W_ih + (((size_t)l2d * 2048 + grow) << 10) + k0
                : W_hh + (((size_t)l2d * 2048 + grow) << 9) + (k0 - 1024);
            float v[8];
            *(float4*)&v[0] = *(const float4*)src;
            *(float4*)&v[4] = *(const float4*)(src + 4);
            uint4 hp, lp; cvt_hilo8(v, hp, lp);
            size_t off = (size_t)R * 1536 + k0;
            *(uint4*)&g_whi[off] = hp;
            *(uint4*)&g_wlo[off] = lp;
        }
    }

    float* wfc_s  = sm + WFC_F;
    float* fcred  = sm + FCRED_F;
    float* tot    = sm + TOT_F;
    float* bias_s = sm + BIAS_F;
    float* hs     = sm + HS_F;

    // resident W_fc rows + combined biases (once)
    #pragma unroll
    for (int p = 0; p < 4; ++p) {
        int i2 = p * NT + tid;
        cp_async16(&wfc_s[i2 * 4], W_fc + ((size_t)(bid << 2)) * 1024 + i2 * 4);
    }
    cp_commit(); cp_wait<0>();
    if (tid < 64) {
        int l = tid >> 5, r = tid & 31;
        int bo = (l * 2 + d) * 2048 + ((r >> 3) << 9) + u0 + (r & 7);
        bias_s[tid] = b_ih[bo] + b_hh[bo];
    }

    grid_sync_(base + 1);
    unsigned gen = base + 1;

    // warp tile: mtile = wid&1 (rows mrow..mrow+15), ntile = wid>>1 (cols n0..n0+7)
    const int mrow = (wid & 1) << 4;
    const int n0   = (wid >> 1) << 3;
    // ldmatrix lane address components (byte offsets within an image)
    const unsigned a_loff = (unsigned)(mrow + (lane & 15)) * PADR + (((unsigned)lane >> 4) << 4);
    const unsigned b_loff = (unsigned)(n0 + (lane & 7)) * PADR + ((((unsigned)lane >> 3) & 1) << 4);

    for (int t = 0; t < T_STEPS; ++t) {
        const int rp = t & 1;
        const int wp = rp ^ 1;

        for (int l = 0; l < 2; ++l) {
            const int l2d = l * 2 + d;
            const __nv_bfloat16* gAh = g_whi + ((size_t)(l2d * 64 + ug) * 32) * 1536;
            const __nv_bfloat16* gAl = g_wlo + ((size_t)(l2d * 64 + ug) * 32) * 1536;

            // stage chunk ch into buffer b: A via cp.async, B via fp32 load+convert+STS
            auto stage = [&](int ch, int b) {
                char* bufb = smc + BUF_BYTE + b * BUFSZB;
                #pragma unroll
                for (int p = 0; p < 4; ++p) {
                    int i = p * NT + tid;          // 1024 = 2 imgs x 32 rows x 16 segs
                    int img = i >> 9, rem = i & 511;
                    int row = rem >> 4, seg = rem & 15;
                    const __nv_bfloat16* srcw = (img ? gAl : gAh)
                        + (size_t)row * 1536 + ch * KC + seg * 8;
                    cp_async16(bufb + img * IMG_A_LO + row * PADR + seg * 16, srcw);
                }
                const int k0 = ch * KC;
                const float* bx; int sx;
                if (l == 0) {
                    if (k0 < 512)       { bx = x_in + (size_t)t * IN_SZ + k0;   sx = T_STEPS * IN_SZ; }
                    else if (k0 < 1024) { bx = &g_prev[0][k0 - 512];            sx = OUT_SZ; }
                    else                { bx = &g_hbuf[rp][0][d][0][k0 - 1024]; sx = LHID; }
                } else {
                    if (k0 < 512)       { bx = &g_hbuf[wp][0][0][0][k0];        sx = LHID; }
                    else if (k0 < 1024) { bx = &g_hbuf[wp][0][1][0][k0 - 512];  sx = LHID; }
                    else                { bx = &g_hbuf[rp][1][d][0][k0 - 1024]; sx = LHID; }
                }
                char* bh = bufb + IMG_B_HI;
                char* bl = bufb + IMG_B_LO;
                #pragma unroll
                for (int it = 0; it < 2; ++it) {
                    int gidx = it * NT + tid;      // 512 = 32 n x 16 segs
                    int n = gidx >> 4, seg = gidx & 15;
                    const float* srow = bx + (size_t)n * sx + seg * 8;
                    float v[8];
                    *(float4*)&v[0] = __ldcg((const float4*)srow);
                    *(float4*)&v[4] = __ldcg((const float4*)(srow + 4));
                    uint4 hp, lp; cvt_hilo8(v, hp, lp);
                    *(uint4*)(bh + n * PADR + seg * 16) = hp;
                    *(uint4*)(bl + n * PADR + seg * 16) = lp;
                }
            };

            float acch[4] = {0.f, 0.f, 0.f, 0.f};
            float accl[4] = {0.f, 0.f, 0.f, 0.f};

            stage(0, 0); cp_commit();
            stage(1, 1); cp_commit();

            for (int ch = 0; ch < NCH; ++ch) {
                if (ch < NCH - 1) cp_wait<1>(); else cp_wait<0>();
                __syncthreads();                   // buffer (ch&1) fully staged

                const unsigned bb = sbase + BUF_BYTE + (ch & 1) * BUFSZB;
                #pragma unroll
                for (int kk8 = 0; kk8 < 8; ++kk8) {
                    const unsigned ka = kk8 * 32;  // 16 bf16 = 32 bytes per k-step
                    unsigned ah[4], al[4], bh2[2], bl2[2];
                    LDSM_X4(ah, bb + a_loff + ka);
                    LDSM_X4(al, bb + IMG_A_LO + a_loff + ka);
                    LDSM_X2(bh2, bb + IMG_B_HI + b_loff + ka);
                    LDSM_X2(bl2, bb + IMG_B_LO + b_loff + ka);
                    MMA_BF16(acch, ah, bh2);
                    MMA_BF16(accl, ah, bl2);
                    MMA_BF16(accl, al, bh2);
                }

                if (ch + 2 < NCH) {
                    __syncthreads();               // all warps done with buffer (ch&1)
                    stage(ch + 2, ch & 1);
                    cp_commit();
                }
            }

            // C fragment -> tot: thread holds (mrow+q, n0+2p), (mrow+q+8, ...) ; q=lane/4, p=lane%4
            {
                int q = lane >> 2, p = lane & 3;
                tot[(mrow + q) * 33 + n0 + 2 * p]     = acch[0] + accl[0];
                tot[(mrow + q) * 33 + n0 + 2 * p + 1] = acch[1] + accl[1];
                tot[(mrow + q + 8) * 33 + n0 + 2 * p]     = acch[2] + accl[2];
                tot[(mrow + q + 8) * 33 + n0 + 2 * p + 1] = acch[3] + accl[3];
            }
            __syncthreads();

            // cell: 256 thr = 32 batch x 8 units
            {
                int c = tid >> 3, j = tid & 7;
                float gi = tot[(0 * 8 + j) * 33 + c] + bias_s[l * 32 + 0 * 8 + j];
                float gf = tot[(1 * 8 + j) * 33 + c] + bias_s[l * 32 + 1 * 8 + j];
                float gg = tot[(2 * 8 + j) * 33 + c] + bias_s[l * 32 + 2 * 8 + j];
                float go = tot[(3 * 8 + j) * 33 + c] + bias_s[l * 32 + 3 * 8 + j];
                float cold = g_c[l][d][c][u0 + j];
                float cn = sigm(gf) * cold + sigm(gi) * tanhf(gg);
                float hn = sigm(go) * tanhf(cn);
                g_c[l][d][c][u0 + j] = cn;
                g_hbuf[wp][l][d][c][u0 + j] = hn;
            }
            grid_sync_(++gen);
        }

        // ---- FC phase: pred = h1cat @ W_fc^T + b_fc (wfc_s resident) ----
        {
            #pragma unroll 8
            for (int p = 0; p < 32; ++p) {
                int idx = p * NT + tid;            // 8192 float4
                int c = idx >> 8, kq = idx & 255;
                int k = kq * 4;
                const float* src = (k < 512) ? &g_hbuf[wp][1][0][c][k]
                                             : &g_hbuf[wp][1][1][c][k - 512];
                cp_async16(&hs[c * 1028 + k], src);
            }
            cp_commit();
            cp_wait<0>();
            __syncthreads();

            const int o0 = bid << 2;
            const int kh = tid >> 7, t2 = tid & 127;
            const int ol = t2 >> 5, c = t2 & 31;
            float a = 0.0f;
            const float* wrow = wfc_s + ol * 1024 + kh * 512;
            const float* xrow = hs + c * 1028 + kh * 512;
            #pragma unroll 8
            for (int q = 0; q < 128; ++q) {
                float4 wv = *(const float4*)(wrow + q * 4);
                float4 xv = *(const float4*)(xrow + q * 4);
                a += wv.x * xv.x; a += wv.y * xv.y;
                a += wv.z * xv.z; a += wv.w * xv.w;
            }
            fcred[kh * 128 + t2] = a;
            __syncthreads();
            if (tid < 128) {
                int c2 = tid >> 2, oo = tid & 3;
                int idx = oo * 32 + c2;
                float v = fcred[idx] + fcred[128 + idx] + b_fc[o0 + oo];
                out[((size_t)c2 * T_STEPS + t) * OUT_SZ + o0 + oo] = v;
                g_prev[c2][o0 + oo] = v;
            }
            grid_sync_(++gen);
        }
    }

    // ---- final h_n, c_n (last write parity = T&1 = 0) ----
    {
        const float* hsrc = &g_hbuf[0][0][0][0][0];
        const float* csrc = &g_c[0][0][0][0];
        for (int e = bid * NT + tid; e < 2 * 2 * BATCH * LHID; e += NB * NT) {
            out[HN_BASE + e] = __ldcg(&hsrc[e]);
            out[HN_BASE + 65536 + e] = __ldcg(&csrc[e]);
        }
    }

    if (bid == 0 && tid == 0) g_base = base + TOTAL_SYNCS;
}

extern "C" void kernel_launch(void* const* d_in, const int* in_sizes, int n_in,
                              void* d_out, int out_size) {
    const float* input_seq = (const float*)d_in[0];
    // d_in[1] = input_lengths (all == T, unused by the reference path)
    const float* W_ih = (const float*)d_in[2];
    const float* W_hh = (const float*)d_in[3];
    const float* b_ih = (const float*)d_in[4];
    const float* b_hh = (const float*)d_in[5];
    const float* W_fc = (const float*)d_in[6];
    const float* b_fc = (const float*)d_in[7];
    float* out = (float*)d_out;

    cudaFuncSetAttribute(ae_kernel, cudaFuncAttributeMaxDynamicSharedMemorySize, SMEM_BYTES);
    ae_kernel<<<NB, NT, SMEM_BYTES>>>(input_seq, W_ih, W_hh, b_ih, b_hh, W_fc, b_fc, out);
}

// round 16
// speedup vs baseline: 1.3200x; 1.3200x over previous
#include <cuda_runtime.h>
#include <cuda_bf16.h>
#include <math.h>

// Problem constants
#define NB        128
#define NT        256
#define T_STEPS   512
#define BATCH     32
#define IN_SZ     512
#define OUT_SZ    512
#define LHID      512
#define KC        256           // k per chunk (never straddles a 512 region boundary)
#define NCH       6             // 1536 / 256
#define HN_BASE   (BATCH * T_STEPS * OUT_SZ)
#define TOTAL_SYNCS 1537u       // 1 + 3*T_STEPS

// Persistent state (device globals; no allocation allowed)
__device__ float g_hbuf[2][2][2][BATCH][LHID];   // fp32 h (FC + h_n)
__device__ float g_c[2][2][BATCH][LHID];
__device__ volatile unsigned g_flag[NB * 32];
__device__ unsigned g_base = 0;
// bf16 hi/lo images (weights converted once; activations written at production)
__device__ __align__(16) __nv_bfloat16 g_whi[4 * 64 * 32 * 1536];      // 25.2 MB
__device__ __align__(16) __nv_bfloat16 g_wlo[4 * 64 * 32 * 1536];      // 25.2 MB
__device__ __align__(16) __nv_bfloat16 g_xh[BATCH * T_STEPS * IN_SZ];  // 16.8 MB
__device__ __align__(16) __nv_bfloat16 g_xl[BATCH * T_STEPS * IN_SZ];
__device__ __align__(16) __nv_bfloat16 g_hh[2][2][2][BATCH][LHID];
__device__ __align__(16) __nv_bfloat16 g_hl[2][2][2][BATCH][LHID];
__device__ __align__(16) __nv_bfloat16 g_ph[BATCH * OUT_SZ];
__device__ __align__(16) __nv_bfloat16 g_pl[BATCH * OUT_SZ];

__device__ __forceinline__ void grid_sync_(unsigned gen) {
    __threadfence();
    __syncthreads();
    if (threadIdx.x == 0) g_flag[blockIdx.x * 32] = gen;
    if (threadIdx.x < NB) { while (g_flag[threadIdx.x * 32] < gen) { } }
    __threadfence();
    __syncthreads();
}

__device__ __forceinline__ float sigm(float x) { return 1.0f / (1.0f + expf(-x)); }

__device__ __forceinline__ void cp_async16(void* smem_dst, const void* gsrc) {
    unsigned saddr = (unsigned)__cvta_generic_to_shared(smem_dst);
    asm volatile("cp.async.cg.shared.global [%0], [%1], 16;\n" :: "r"(saddr), "l"(gsrc));
}
__device__ __forceinline__ void cp_commit() { asm volatile("cp.async.commit_group;\n"); }
template <int N> __device__ __forceinline__ void cp_wait() {
    asm volatile("cp.async.wait_group %0;\n" :: "n"(N));
}

__device__ __forceinline__ unsigned short bf2u(__nv_bfloat16 h) {
    return *reinterpret_cast<unsigned short*>(&h);
}
__device__ __forceinline__ void cvt_hilo8(const float* v, uint4& hp, uint4& lp) {
    unsigned hw[4], lw[4];
    #pragma unroll
    for (int i = 0; i < 4; ++i) {
        __nv_bfloat16 h0 = __float2bfloat16(v[2*i]), h1 = __float2bfloat16(v[2*i+1]);
        float f0 = __bfloat162float(h0), f1 = __bfloat162float(h1);
        __nv_bfloat16 l0 = __float2bfloat16(v[2*i] - f0), l1 = __float2bfloat16(v[2*i+1] - f1);
        hw[i] = (unsigned)bf2u(h0) | ((unsigned)bf2u(h1) << 16);
        lw[i] = (unsigned)bf2u(l0) | ((unsigned)bf2u(l1) << 16);
    }
    hp = make_uint4(hw[0], hw[1], hw[2], hw[3]);
    lp = make_uint4(lw[0], lw[1], lw[2], lw[3]);
}

// HMMA m16n8k16 bf16->f32 (sm_80 PTX; valid on generic sm_103 target)
#define MMA_BF16(d, a, b) \
    asm volatile("mma.sync.aligned.m16n8k16.row.col.f32.bf16.bf16.f32 " \
                 "{%0,%1,%2,%3}, {%4,%5,%6,%7}, {%8,%9}, {%0,%1,%2,%3};" \
                 : "+f"(d[0]), "+f"(d[1]), "+f"(d[2]), "+f"(d[3]) \
                 : "r"(a[0]), "r"(a[1]), "r"(a[2]), "r"(a[3]), "r"(b[0]), "r"(b[1]))
#define LDSM_X4(r, addr) \
    asm volatile("ldmatrix.sync.aligned.m8n8.x4.shared.b16 {%0,%1,%2,%3}, [%4];" \
                 : "=r"(r[0]), "=r"(r[1]), "=r"(r[2]), "=r"(r[3]) : "r"(addr))
#define LDSM_X2(r, addr) \
    asm volatile("ldmatrix.sync.aligned.m8n8.x2.shared.b16 {%0,%1}, [%2];" \
                 : "=r"(r[0]), "=r"(r[1]) : "r"(addr))

// smem byte layout:
//   wfc [0,16384) | fcred [16384,17408) | tot [17408,21632) | bias [21632,21888)
//   3 buffers @ BUF_B, each 67584: { Ahi@0, Alo@16896, Bhi@33792, Blo@50688 }
//   FC overlay: hs (131584 B) at HS_B = buffers 1+2 region (buffer 0 stays live
//   for next-step chunk-0 pre-issue)
#define WFC_B    0
#define FCRED_B  16384
#define TOT_B    17408
#define BIAS_B   21632
#define BUF_B    21888
#define BUFSZB   67584
#define IMGSZ    16896          // one 32-row bf16 image, row stride PADR2
#define PADR2    528            // (256+8)*2 bytes; 528 % 128 = 16 -> conflict-staggered
#define HS_B     (BUF_B + BUFSZB)       // 89472
#define SMEM_BYTES 224640

__global__ void __launch_bounds__(NT, 1)
ae_kernel(const float* __restrict__ x_in,
          const float* __restrict__ W_ih, const float* __restrict__ W_hh,
          const float* __restrict__ b_ih, const float* __restrict__ b_hh,
          const float* __restrict__ W_fc, const float* __restrict__ b_fc,
          float* __restrict__ out)
{
    extern __shared__ float sm[];
    char* smc = (char*)sm;
    const int tid = threadIdx.x;
    const int bid = blockIdx.x;
    const int wid = tid >> 5;
    const int lane = tid & 31;
    const unsigned sbase = (unsigned)__cvta_generic_to_shared(sm);
    const unsigned base = g_base;

    const int d  = bid >> 6;
    const int ug = bid & 63;
    const int u0 = ug << 3;

    // ---- init state + one-time conversions (idempotent every launch) ----
    {
        const int gid = bid * NT + tid;
        float* h0 = &g_hbuf[0][0][0][0][0];
        for (int e = gid; e < 2 * 2 * BATCH * LHID; e += NB * NT) h0[e] = 0.0f;
        float* c0 = &g_c[0][0][0][0];
        for (int e = gid; e < 2 * 2 * BATCH * LHID; e += NB * NT) c0[e] = 0.0f;
        unsigned short* hhz = (unsigned short*)&g_hh[0][0][0][0][0];
        unsigned short* hlz = (unsigned short*)&g_hl[0][0][0][0][0];
        for (int e = gid; e < 2 * 2 * 2 * BATCH * LHID; e += NB * NT) { hhz[e] = 0; hlz[e] = 0; }
        unsigned short* phz = (unsigned short*)g_ph;
        unsigned short* plz = (unsigned short*)g_pl;
        for (int e = gid; e < BATCH * OUT_SZ; e += NB * NT) { phz[e] = 0; plz[e] = 0; }

        // weight images: row R = ((l2d*64+ug)*32 + r), r = gate*8+j -> W row gate*512+ug*8+j
        for (int g = gid; g < 4 * 64 * 32 * 192; g += NB * NT) {
            int seg = g % 192, R = g / 192;
            int l2d = R >> 11, ugr = (R >> 5) & 63, r = R & 31;
            int grow = ((r >> 3) << 9) + (ugr << 3) + (r & 7);
            int k0 = seg * 8;
            const float* src = (k0 < 1024)
                ? W_ih + (((size_t)l2d * 2048 + grow) << 10) + k0
                : W_hh + (((size_t)l2d * 2048 + grow) << 9) + (k0 - 1024);
            float v[8];
            *(float4*)&v[0] = *(const float4*)src;
            *(float4*)&v[4] = *(const float4*)(src + 4);
            uint4 hp, lp; cvt_hilo8(v, hp, lp);
            size_t off = (size_t)R * 1536 + k0;
            *(uint4*)&g_whi[off] = hp;
            *(uint4*)&g_wlo[off] = lp;
        }
        // x_in -> bf16 hi/lo image, same [B][T][IN] order
        for (int g = gid; g < BATCH * T_STEPS * IN_SZ / 8; g += NB * NT) {
            const float* src = x_in + (size_t)g * 8;
            float v[8];
            *(float4*)&v[0] = *(const float4*)src;
            *(float4*)&v[4] = *(const float4*)(src + 4);
            uint4 hp, lp; cvt_hilo8(v, hp, lp);
            *(uint4*)&g_xh[(size_t)g * 8] = hp;
            *(uint4*)&g_xl[(size_t)g * 8] = lp;
        }
    }

    float* wfc_s  = (float*)(smc + WFC_B);
    float* fcred  = (float*)(smc + FCRED_B);
    float* tot    = (float*)(smc + TOT_B);
    float* bias_s = (float*)(smc + BIAS_B);
    float* hs     = (float*)(smc + HS_B);

    // resident W_fc rows + combined biases (once)
    #pragma unroll
    for (int p = 0; p < 4; ++p) {
        int i2 = p * NT + tid;
        cp_async16(&wfc_s[i2 * 4], W_fc + ((size_t)(bid << 2)) * 1024 + i2 * 4);
    }
    cp_commit(); cp_wait<0>();
    if (tid < 64) {
        int l = tid >> 5, r = tid & 31;
        int bo = (l * 2 + d) * 2048 + ((r >> 3) << 9) + u0 + (r & 7);
        bias_s[tid] = b_ih[bo] + b_hh[bo];
    }

    grid_sync_(base + 1);
    unsigned gen = base + 1;

    // warp tile: 2 m-tiles x 4 n-tiles
    const int mrow = (wid & 1) << 4;
    const int n0   = (wid >> 1) << 3;
    const unsigned a_loff = (unsigned)(mrow + (lane & 15)) * PADR2 + (((unsigned)lane >> 4) << 4);
    const unsigned b_loff = (unsigned)(n0 + (lane & 7)) * PADR2 + ((((unsigned)lane >> 3) & 1) << 4);

    // stage A (weights) of layer l, chunk ch into buffer b: flat cp.async, 8/thread
    auto stageA = [&](int l, int ch, int b) {
        const __nv_bfloat16* gAh = g_whi + (size_t)((l * 2 + d) * 64 + ug) * 32 * 1536;
        const __nv_bfloat16* gAl = g_wlo + (size_t)((l * 2 + d) * 64 + ug) * 32 * 1536;
        char* bufb = smc + BUF_B + b * BUFSZB;
        #pragma unroll
        for (int p = 0; p < 8; ++p) {
            int i = p * NT + tid;                  // 2048 = 2 img x 32 rows x 32 segs
            int img = i >> 10, rem = i & 1023;
            int row = rem >> 5, seg = rem & 31;
            const __nv_bfloat16* src = (img ? gAl : gAh) + (size_t)row * 1536 + ch * KC + seg * 8;
            cp_async16(bufb + img * IMGSZ + row * PADR2 + seg * 16, src);
        }
    };
    // stage B (activations, pre-converted bf16): flat cp.async, 8/thread
    auto stageB = [&](int l, int ch, int b, int t, int rp, int wp) {
        const int k0 = ch * KC;
        const __nv_bfloat16 *bh_, *bl_; int sx;
        if (l == 0) {
            if (k0 < 512)       { bh_ = g_xh + (size_t)t * IN_SZ + k0;
                                  bl_ = g_xl + (size_t)t * IN_SZ + k0;  sx = T_STEPS * IN_SZ; }
            else if (k0 < 1024) { bh_ = g_ph + (k0 - 512);
                                  bl_ = g_pl + (k0 - 512);              sx = OUT_SZ; }
            else                { bh_ = &g_hh[rp][0][d][0][k0 - 1024];
                                  bl_ = &g_hl[rp][0][d][0][k0 - 1024];  sx = LHID; }
        } else {
            if (k0 < 512)       { bh_ = &g_hh[wp][0][0][0][k0];
                                  bl_ = &g_hl[wp][0][0][0][k0];         sx = LHID; }
            else if (k0 < 1024) { bh_ = &g_hh[wp][0][1][0][k0 - 512];
                                  bl_ = &g_hl[wp][0][1][0][k0 - 512];   sx = LHID; }
            else                { bh_ = &g_hh[rp][1][d][0][k0 - 1024];
                                  bl_ = &g_hl[rp][1][d][0][k0 - 1024];  sx = LHID; }
        }
        char* bufb = smc + BUF_B + b * BUFSZB + 2 * IMGSZ;
        #pragma unroll
        for (int p = 0; p < 8; ++p) {
            int i = p * NT + tid;
            int img = i >> 10, rem = i & 1023;
            int n = rem >> 5, seg = rem & 31;
            const __nv_bfloat16* src = (img ? bl_ : bh_) + (size_t)n * sx + seg * 8;
            cp_async16(bufb + img * IMGSZ + n * PADR2 + seg * 16, src);
        }
    };

    for (int t = 0; t < T_STEPS; ++t) {
        const int rp = t & 1;
        const int wp = rp ^ 1;

        for (int l = 0; l < 2; ++l) {
            // establish invariant: chunks 0,1,2 committed as 3 groups
            if (t == 0 && l == 0) {
                stageA(0, 0, 0); stageB(0, 0, 0, t, rp, wp); cp_commit();
            } else if (l == 1) {
                stageB(1, 0, 0, t, rp, wp); cp_commit();     // A(0) pre-issued pre-sync
            }
            // (l==0, t>0): chunk 0 was fully committed during the FC phase
            stageA(l, 1, 1); stageB(l, 1, 1, t, rp, wp); cp_commit();
            stageA(l, 2, 2); stageB(l, 2, 2, t, rp, wp); cp_commit();

            float acch[4] = {0.f, 0.f, 0.f, 0.f};
            float accl[4] = {0.f, 0.f, 0.f, 0.f};

            #pragma unroll 1
            for (int ch = 0; ch < NCH; ++ch) {
                if (ch < 4) cp_wait<2>(); else if (ch == 4) cp_wait<1>(); else cp_wait<0>();
                __syncthreads();

                const unsigned bb = sbase + BUF_B + (unsigned)(ch % 3) * BUFSZB;
                #pragma unroll
                for (int kk = 0; kk < 16; ++kk) {
                    const unsigned ka = kk * 32;
                    unsigned ah[4], al[4], bh2[2], bl2[2];
                    LDSM_X4(ah, bb + a_loff + ka);
                    LDSM_X4(al, bb + IMGSZ + a_loff + ka);
                    LDSM_X2(bh2, bb + 2 * IMGSZ + b_loff + ka);
                    LDSM_X2(bl2, bb + 3 * IMGSZ + b_loff + ka);
                    MMA_BF16(acch, ah, bh2);
                    MMA_BF16(accl, ah, bl2);
                    MMA_BF16(accl, al, bh2);
                }

                if (ch + 3 < NCH) {
                    __syncthreads();               // all warps done with buffer ch%3
                    stageA(l, ch + 3, ch % 3);
                    stageB(l, ch + 3, ch % 3, t, rp, wp);
                    cp_commit();
                }
            }

            // C fragments -> tot (32x33)
            {
                int q = lane >> 2, p = lane & 3;
                tot[(mrow + q) * 33 + n0 + 2 * p]         = acch[0] + accl[0];
                tot[(mrow + q) * 33 + n0 + 2 * p + 1]     = acch[1] + accl[1];
                tot[(mrow + q + 8) * 33 + n0 + 2 * p]     = acch[2] + accl[2];
                tot[(mrow + q + 8) * 33 + n0 + 2 * p + 1] = acch[3] + accl[3];
            }
            __syncthreads();

            // cell: 256 thr = 32 batch x 8 units; write fp32 + bf16 hi/lo h
            {
                int c = tid >> 3, j = tid & 7;
                float gi = tot[(0 * 8 + j) * 33 + c] + bias_s[l * 32 + 0 * 8 + j];
                float gf = tot[(1 * 8 + j) * 33 + c] + bias_s[l * 32 + 1 * 8 + j];
                float gg = tot[(2 * 8 + j) * 33 + c] + bias_s[l * 32 + 2 * 8 + j];
                float go = tot[(3 * 8 + j) * 33 + c] + bias_s[l * 32 + 3 * 8 + j];
                float cold = g_c[l][d][c][u0 + j];
                float cn = sigm(gf) * cold + sigm(gi) * tanhf(gg);
                float hn = sigm(go) * tanhf(cn);
                g_c[l][d][c][u0 + j] = cn;
                g_hbuf[wp][l][d][c][u0 + j] = hn;
                __nv_bfloat16 hh = __float2bfloat16(hn);
                g_hh[wp][l][d][c][u0 + j] = hh;
                g_hl[wp][l][d][c][u0 + j] = __float2bfloat16(hn - __bfloat162float(hh));
            }

            if (l == 0) stageA(1, 0, 0);   // pre-issue next layer's A(0), uncommitted
            grid_sync_(++gen);
        }

        // ---- FC phase: pred = h1cat @ W_fc^T + b_fc ----
        {
            // hs over buffers 1,2 only; buffer 0 reserved for next-step chunk 0
            #pragma unroll 8
            for (int p = 0; p < 32; ++p) {
                int idx = p * NT + tid;            // 8192 float4
                int c = idx >> 8, kq = idx & 255;
                int k = kq * 4;
                const float* src = (k < 512) ? &g_hbuf[wp][1][0][c][k]
                                             : &g_hbuf[wp][1][1][c][k - 512];
                cp_async16(&hs[c * 1028 + k], src);
            }
            cp_commit();                           // group: hs
            if (t + 1 < T_STEPS) {                 // next-step l0 chunk 0 (x_in only -> safe)
                stageA(0, 0, 0);
                stageB(0, 0, 0, t + 1, wp, rp);    // rp' = wp, wp' = rp
                cp_commit();                       // group: chunk 0
                cp_wait<1>();                      // hs done; chunk 0 may stay in flight
            } else {
                cp_wait<0>();
            }
            __syncthreads();

            const int o0 = bid << 2;
            const int kh = tid >> 7, t2 = tid & 127;
            const int ol = t2 >> 5, c = t2 & 31;
            float a = 0.0f;
            const float* wrow = wfc_s + ol * 1024 + kh * 512;
            const float* xrow = hs + c * 1028 + kh * 512;
            #pragma unroll 8
            for (int q = 0; q < 128; ++q) {
                float4 wv = *(const float4*)(wrow + q * 4);
                float4 xv = *(const float4*)(xrow + q * 4);
                a += wv.x * xv.x; a += wv.y * xv.y;
                a += wv.z * xv.z; a += wv.w * xv.w;
            }
            fcred[kh * 128 + t2] = a;
            __syncthreads();
            if (tid < 128) {
                int c2 = tid >> 2, oo = tid & 3;
                int idx = oo * 32 + c2;
                float v = fcred[idx] + fcred[128 + idx] + b_fc[o0 + oo];
                out[((size_t)c2 * T_STEPS + t) * OUT_SZ + o0 + oo] = v;
                __nv_bfloat16 vh = __float2bfloat16(v);
                g_ph[c2 * OUT_SZ + o0 + oo] = vh;
                g_pl[c2 * OUT_SZ + o0 + oo] = __float2bfloat16(v - __bfloat162float(vh));
            }
            grid_sync_(++gen);
        }
    }

    // ---- final h_n, c_n (last write parity = T&1 = 0) ----
    {
        const float* hsrc = &g_hbuf[0][0][0][0][0];
        const float* csrc = &g_c[0][0][0][0];
        for (int e = bid * NT + tid; e < 2 * 2 * BATCH * LHID; e += NB * NT) {
            out[HN_BASE + e] = __ldcg(&hsrc[e]);
            out[HN_BASE + 65536 + e] = __ldcg(&csrc[e]);
        }
    }

    if (bid == 0 && tid == 0) g_base = base + TOTAL_SYNCS;
}

extern "C" void kernel_launch(void* const* d_in, const int* in_sizes, int n_in,
                              void* d_out, int out_size) {
    const float* input_seq = (const float*)d_in[0];
    // d_in[1] = input_lengths (all == T, unused by the reference path)
    const float* W_ih = (const float*)d_in[2];
    const float* W_hh = (const float*)d_in[3];
    const float* b_ih = (const float*)d_in[4];
    const float* b_hh = (const float*)d_in[5];
    const float* W_fc = (const float*)d_in[6];
    const float* b_fc = (const float*)d_in[7];
    float* out = (float*)d_out;

    cudaFuncSetAttribute(ae_kernel, cudaFuncAttributeMaxDynamicSharedMemorySize, SMEM_BYTES);
    ae_kernel<<<NB, NT, SMEM_BYTES>>>(input_seq, W_ih, W_hh, b_ih, b_hh, W_fc, b_fc, out);
}